// round 15
// baseline (speedup 1.0000x reference)
#include <cuda_runtime.h>

#define NQ 12
#define THREADS 256
#define PI_F 3.14159265358979323846f
typedef unsigned long long u64;

// Fused staging block (written by setup_kernel block 20), copied once into constant.
struct CParams {
    u64      G[165];     // RY coefficients, layers 1..5 (33 u64/layer)
    unsigned RM[72];     // CNOT masks: fwd layers 0..4, inverse layer 5
    float2   U0[48];     // layer-0 full Rot matrices (init fold)
};
__device__   CParams g_S;
__constant__ CParams cS;

__device__ ulonglong2 g_D2[5 * 2048];  // merged-diagonal, SoA-packed over (m, m+8):
                                       // entry (l,m,t) = {pk2(c_j0,c_j1), pk2(s_j0,s_j1)},
                                       // j0=(t<<4)|m, j1=j0|8; index (l<<11)|(m<<8)|t

__device__ __forceinline__ float2 cmul(float2 a, float2 b) {
    return make_float2(a.x * b.x - a.y * b.y, a.x * b.y + a.y * b.x);
}
__device__ __forceinline__ u64 pk2(float a, float b) {
    u64 r; asm("mov.b64 %0,{%1,%2};" : "=l"(r) : "f"(a), "f"(b)); return r;
}
__device__ __forceinline__ void unpk(u64 x, float& a, float& b) {
    asm("mov.b64 {%0,%1},%2;" : "=f"(a), "=f"(b) : "l"(x));
}
__device__ __forceinline__ u64 m2(u64 a, u64 b) {
    u64 d; asm("mul.rn.f32x2 %0,%1,%2;" : "=l"(d) : "l"(a), "l"(b)); return d;
}
__device__ __forceinline__ u64 fma2(u64 a, u64 b, u64 c) {
    u64 d; asm("fma.rn.f32x2 %0,%1,%2,%3;" : "=l"(d) : "l"(a), "l"(b), "l"(c)); return d;
}
__device__ __forceinline__ u64 swp(u64 x) {
    float lo, hi; unpk(x, lo, hi); return pk2(hi, lo);
}

// Forward CNOT-ring mask for layer l (0..4): image of basis bit bb under ring fold.
__device__ __forceinline__ unsigned ring_fwd_mask(int l, int bb) {
    unsigned i = 1u << bb;
    int r = (l % (NQ - 1)) + 1;
    for (int w = NQ - 1; w >= 0; --w)
        i ^= ((i >> w) & 1u) << ((w + r) % NQ);
    return i;
}

// ---------------------------------------------------------------------------
// Fused setup kernel.
//  blocks 0..19 (512 thr): diagonal table (10240 entries), ring masks inline.
//  block 20: staging struct g_S (layer-0 Rot fold, RY coeffs, CNOT masks).
// ---------------------------------------------------------------------------
__global__ void setup_kernel(const float* __restrict__ weights) {
    int tid = threadIdx.x;

    if (blockIdx.x == 20) {
        __shared__ float2 U[NQ][2][2];
        for (int w = tid; w < NQ; w += blockDim.x) {
            float phi = weights[w * 3 + 0];
            float th  = weights[w * 3 + 1];
            float om  = weights[w * 3 + 2];
            float s = sinf(0.5f * th), c = cosf(0.5f * th);
            float ap = 0.5f * (phi + om), am = 0.5f * (phi - om);
            float sap = sinf(ap), cap = cosf(ap);
            float sam = sinf(am), cam = cosf(am);
            U[w][0][0] = make_float2(cap * c, -sap * c);
            U[w][0][1] = make_float2(-cam * s, -sam * s);
            U[w][1][0] = make_float2(cam * s, -sam * s);
            U[w][1][1] = make_float2(cap * c, sap * c);
        }
        __syncthreads();
        for (int e = tid; e < NQ * 4; e += blockDim.x) {
            int w = e >> 2;
            g_S.U0[e] = U[w][(e >> 1) & 1][e & 1];
        }
        // RY coefficients for layers 1..5 (33 u64/layer, 11/config)
        if (tid < 15) {
            int l = tid / 3 + 1, c = tid % 3;
            int base = (l - 1) * 33 + c * 11;
            for (int bit = 0; bit < 4; bit++) {
                int q = c * 4 + bit;
                float th = weights[(l * NQ + q) * 3 + 1];
                float cc = cosf(0.5f * th), ss = sinf(0.5f * th);
                if (bit < 3) {
                    g_S.G[base + bit * 3 + 0] = pk2(cc, cc);
                    g_S.G[base + bit * 3 + 1] = pk2(ss, ss);
                    g_S.G[base + bit * 3 + 2] = pk2(-ss, -ss);
                } else {
                    g_S.G[base + 9]  = pk2(cc, cc);
                    g_S.G[base + 10] = pk2(-ss, ss);
                }
            }
        }
        // CNOT-ring masks: forward for layers 0..4, inverse for layer 5.
        for (int e = tid; e < 6 * NQ; e += blockDim.x) {
            int l = e / NQ, bb = e % NQ;
            unsigned i;
            if (l < 5) {
                i = ring_fwd_mask(l, bb);
            } else {
                i = 1u << bb;
                int r = (5 % (NQ - 1)) + 1;
                for (int w = 0; w < NQ; ++w)
                    i ^= ((i >> w) & 1u) << ((w + r) % NQ);
            }
            g_S.RM[e] = i;
        }
        return;
    }

    // Diagonal-table blocks. Entry math identical to R11:
    //   alpha(j) = sum_w (phi_{tl,w}/2)(2 b_w(j) - 1)
    //            + [tl>=2] sum_w (omega_{tl-1,w}/2)(2 b_w(R_{tl-1}(j)) - 1)
    int idx = blockIdx.x * 512 + tid;            // 0 .. 10239
    int l = idx >> 11;                           // 0..4 -> table layer l+1
    int rem = idx & 2047;
    int m = rem >> 8, t = rem & 255;
    float al[2];
#pragma unroll
    for (int h = 0; h < 2; h++) {
        unsigned j = ((unsigned)t << 4) | (unsigned)m | ((unsigned)h << 3);
        float a = 0.f;
        for (int w = 0; w < NQ; w++) {
            float phi = weights[((l + 1) * NQ + w) * 3 + 0];
            a += 0.5f * phi * (((j >> w) & 1u) ? 1.f : -1.f);
        }
        if (l >= 1) {
            unsigned rj = 0;
            for (int bb = 0; bb < NQ; bb++)
                if ((j >> bb) & 1u) rj ^= ring_fwd_mask(l, bb);
            for (int w = 0; w < NQ; w++) {
                float om = weights[(l * NQ + w) * 3 + 2];
                a += 0.5f * om * (((rj >> w) & 1u) ? 1.f : -1.f);
            }
        }
        al[h] = a;
    }
    ulonglong2 e;
    e.x = pk2(cosf(al[0]), cosf(al[1]));
    e.y = pk2(sinf(al[0]), sinf(al[1]));
    g_D2[((unsigned)l << 11) | ((unsigned)m << 8) | (unsigned)t] = e;
}

// ---------------------------------------------------------------------------
// RY gates on SoA packed registers (RE[m],IM[m] pack amp pair (m, m+8))
// ---------------------------------------------------------------------------
template <int Q>
__device__ __forceinline__ void bgate_ry(u64* RE, u64* IM, const u64* __restrict__ g) {
    u64 cc = g[0], ss = g[1], ns = g[2];
#pragma unroll
    for (int h = 0; h < 4; h++) {
        const int a = ((h >> Q) << (Q + 1)) | (h & ((1 << Q) - 1));
        const int bq = a + (1 << Q);
        u64 x0r = RE[a], x0i = IM[a], x1r = RE[bq], x1i = IM[bq];
        u64 y0r = m2(cc, x0r); y0r = fma2(ns, x1r, y0r);
        u64 y1r = m2(ss, x0r); y1r = fma2(cc, x1r, y1r);
        u64 y0i = m2(cc, x0i); y0i = fma2(ns, x1i, y0i);
        u64 y1i = m2(ss, x0i); y1i = fma2(cc, x1i, y1i);
        RE[a] = y0r; IM[a] = y0i; RE[bq] = y1r; IM[bq] = y1i;
    }
}

__device__ __forceinline__ void pgate_ry(u64* RE, u64* IM, const u64* __restrict__ g) {
    u64 P1 = g[0], P2 = g[1];     // (c,c), (-s,s)
#pragma unroll
    for (int m = 0; m < 8; m++) {
        u64 xr = RE[m], xi = IM[m];
        u64 yr = m2(P1, xr); yr = fma2(P2, swp(xr), yr);
        u64 yi = m2(P1, xi); yi = fma2(P2, swp(xi), yi);
        RE[m] = yr; IM[m] = yi;
    }
}

// ---------------------------------------------------------------------------
// Main kernel — R14 structure with the 5-layer loop FULLY UNROLLED:
// per-layer constant offsets become immediates; ptxas gets cross-layer
// scheduling windows (dd prefetch / mask setup can drift into prior tail).
// SMEM SoA, swizzle phi(j) = j ^ ((j>>4)&31).
// Config A: j=(t<<4)|m  Config B: j=(thi<<8)|(m<<4)|tlo  Config C: j=(m<<8)|t
// ---------------------------------------------------------------------------
__global__ void __launch_bounds__(THREADS, 4) qvl_kernel(
    const float* __restrict__ v, const float* __restrict__ W,
    const float* __restrict__ bc, float* __restrict__ out) {
    __shared__ float  SS[8192];        // [0..4095]=re, [4096..8191]=im
    __shared__ float2 sAH[40];
    __shared__ int    sWtab[12];
#define SRE(i) SS[(i)]
#define SIM(i) SS[4096 + (i)]

    int b = blockIdx.x, t = threadIdx.x;
    int lane = t & 31, warp = t >> 5;

    if (t < 12) {
        unsigned w = t;
        int s = (int)(((cS.RM[68] >> w) & 1u) | (((cS.RM[69] >> w) & 1u) << 1)
                    | (((cS.RM[70] >> w) & 1u) << 2) | (((cS.RM[71] >> w) & 1u) << 3));
        sWtab[t] = s;
    }

    // Angles: x_w = tanh(v[b]·W[w] + b[w]) * pi, fold layer-0 Rot
    const float* vrow = v + (size_t)b * 512;
    for (int w = warp; w < NQ; w += 8) {
        const float* Wr = W + w * 512;
        float acc = 0.f;
#pragma unroll
        for (int q = 0; q < 16; q++)
            acc = fmaf(vrow[lane + 32 * q], Wr[lane + 32 * q], acc);
#pragma unroll
        for (int o = 16; o; o >>= 1) acc += __shfl_xor_sync(0xFFFFFFFFu, acc, o);
        if (lane == 0) {
            float x = tanhf(acc + bc[w]) * PI_F;
            float ch = cosf(0.5f * x), sh = sinf(0.5f * x);
            float2 u00 = cS.U0[w * 4 + 0], u01 = cS.U0[w * 4 + 1];
            float2 u10 = cS.U0[w * 4 + 2], u11 = cS.U0[w * 4 + 3];
            sAH[2 * w + 0] = make_float2(u00.x * ch + u01.x * sh, u00.y * ch + u01.y * sh);
            sAH[2 * w + 1] = make_float2(u10.x * ch + u11.x * sh, u10.y * ch + u11.y * sh);
        }
    }
    __syncthreads();
    if (t < 16) {
        float2 h = sAH[16 + (t & 1)];
        h = cmul(h, sAH[18 + ((t >> 1) & 1)]);
        h = cmul(h, sAH[20 + ((t >> 2) & 1)]);
        h = cmul(h, sAH[22 + ((t >> 3) & 1)]);
        sAH[24 + t] = h;
    }
    __syncthreads();

    unsigned xC = (unsigned)t ^ (((unsigned)t >> 4) & 15u);
    unsigned xA = ((unsigned)t << 4) ^ ((unsigned)t & 31u);
    unsigned xB = ((((unsigned)t >> 4) << 8) | ((unsigned)t & 15u)) ^ ((((unsigned)t >> 4) & 1u) << 4);

    // Product-state init -> config C positions
    {
        float2 tp = sAH[t & 1];
#pragma unroll
        for (int w = 1; w < 8; w++)
            tp = cmul(tp, sAH[2 * w + ((t >> w) & 1)]);
#pragma unroll
        for (int m = 0; m < 16; m++) {
            float2 a = cmul(tp, sAH[24 + m]);
            unsigned ad = ((unsigned)m << 8) ^ xC ^ (((unsigned)m & 1u) << 4);
            SRE(ad) = a.x; SIM(ad) = a.y;
        }
    }
    __syncthreads();

    u64 RE[8], IM[8];

#pragma unroll 5
    for (int l = 1; l <= 5; l++) {
        const u64* gl = cS.G + (l - 1) * 33;
        const unsigned* rm = cS.RM + (l - 1) * 12;

        // ---- prefetch SoA-packed diagonal entries (coalesced LDG.128) ----
        const ulonglong2* Dl = g_D2 + ((l - 1) << 11) + t;
        ulonglong2 dd[8];
#pragma unroll
        for (int m = 0; m < 8; m++)
            dd[m] = Dl[m << 8];

        // ---- masked read into config A (CNOT ring of layer l-1 folded) ----
        unsigned sb = 0;
#pragma unroll
        for (int k = 0; k < 8; k++)
            sb ^= rm[4 + k] & (unsigned)(-(int)((t >> k) & 1));
        unsigned sbz = sb ^ ((sb >> 4) & 31u);
        unsigned r0 = rm[0], r1 = rm[1], r2 = rm[2], r3 = rm[3];
        unsigned z0 = r0 ^ ((r0 >> 4) & 31u);
        unsigned z1 = r1 ^ ((r1 >> 4) & 31u);
        unsigned z2 = r2 ^ ((r2 >> 4) & 31u);
        unsigned z3 = r3 ^ ((r3 >> 4) & 31u);
#pragma unroll
        for (int m = 0; m < 8; m++) {
            unsigned a0 = sbz;
            if (m & 1) a0 ^= z0;
            if (m & 2) a0 ^= z1;
            if (m & 4) a0 ^= z2;
            unsigned a1 = a0 ^ z3;
            RE[m] = pk2(SRE(a0), SRE(a1));
            IM[m] = pk2(SIM(a0), SIM(a1));
        }

        // ---- merged diagonal (pushed-through RZ walls), dest amp j=(t<<4)|m ----
#pragma unroll
        for (int m = 0; m < 8; m++) {
            u64 c2 = dd[m].x;
            u64 s2 = dd[m].y;
            u64 ns2 = s2 ^ 0x8000000080000000ULL;
            u64 nr = m2(c2, RE[m]); nr = fma2(ns2, IM[m], nr);
            u64 ni = m2(c2, IM[m]); ni = fma2(s2, RE[m], ni);
            RE[m] = nr; IM[m] = ni;
        }

        bgate_ry<0>(RE, IM, gl + 0);   // q0
        bgate_ry<1>(RE, IM, gl + 3);   // q1
        bgate_ry<2>(RE, IM, gl + 6);   // q2
        pgate_ry(RE, IM, gl + 9);      // q3 (pack bit)
        __syncthreads();               // all masked reads done before write A
#pragma unroll
        for (int m = 0; m < 8; m++) {  // write A
            unsigned a0 = xA ^ (unsigned)m, a1 = a0 ^ 8u;
            float lo, hi;
            unpk(RE[m], lo, hi); SRE(a0) = lo; SRE(a1) = hi;
            unpk(IM[m], lo, hi); SIM(a0) = lo; SIM(a1) = hi;
        }
        __syncwarp();                  // A<->B exchange within 16-thread groups
#pragma unroll
        for (int m = 0; m < 8; m++) {  // read B
            unsigned a0 = xB ^ (unsigned)(m * 17), a1 = a0 ^ 136u;
            RE[m] = pk2(SRE(a0), SRE(a1));
            IM[m] = pk2(SIM(a0), SIM(a1));
        }
        bgate_ry<0>(RE, IM, gl + 11);  // q4
        bgate_ry<1>(RE, IM, gl + 14);  // q5
        bgate_ry<2>(RE, IM, gl + 17);  // q6
        pgate_ry(RE, IM, gl + 20);     // q7 (pack bit)
#pragma unroll
        for (int m = 0; m < 8; m++) {  // write B (same per-thread set)
            unsigned a0 = xB ^ (unsigned)(m * 17), a1 = a0 ^ 136u;
            float lo, hi;
            unpk(RE[m], lo, hi); SRE(a0) = lo; SRE(a1) = hi;
            unpk(IM[m], lo, hi); SIM(a0) = lo; SIM(a1) = hi;
        }
        __syncthreads();               // B->C crosses the whole CTA
#pragma unroll
        for (int m = 0; m < 8; m++) {  // read C
            unsigned a0 = xC ^ ((unsigned)m << 8) ^ (((unsigned)m & 1u) << 4);
            unsigned a1 = a0 ^ 2048u;
            RE[m] = pk2(SRE(a0), SRE(a1));
            IM[m] = pk2(SIM(a0), SIM(a1));
        }
        bgate_ry<0>(RE, IM, gl + 22);  // q8
        bgate_ry<1>(RE, IM, gl + 25);  // q9
        bgate_ry<2>(RE, IM, gl + 28);  // q10
        pgate_ry(RE, IM, gl + 31);     // q11 (pack bit)
        if (l < 5) {
#pragma unroll
            for (int m = 0; m < 8; m++) {  // write C (same per-thread set)
                unsigned a0 = xC ^ ((unsigned)m << 8) ^ (((unsigned)m & 1u) << 4);
                unsigned a1 = a0 ^ 2048u;
                float lo, hi;
                unpk(RE[m], lo, hi); SRE(a0) = lo; SRE(a1) = hi;
                unpk(IM[m], lo, hi); SIM(a0) = lo; SIM(a1) = hi;
            }
            __syncthreads();
        }
    }

    // ---- Expvals via 4-level Walsh transform over the m-bits ----
    // (Final RZ wall is a pure phase: cancels in |amp|^2. Ring_5 via inverse masks.)
    {
        unsigned ptw = 0;
#pragma unroll
        for (int k = 0; k < 8; k++)
            ptw ^= cS.RM[60 + k] & (unsigned)(-(int)((t >> k) & 1));

        float p[16];
#pragma unroll
        for (int m = 0; m < 8; m++) {
            u64 P = m2(RE[m], RE[m]);
            P = fma2(IM[m], IM[m], P);
            unpk(P, p[m], p[m + 8]);
        }
#pragma unroll
        for (int st = 1; st < 16; st <<= 1) {
#pragma unroll
            for (int i = 0; i < 16; i++) {
                if (!(i & st)) {
                    float a = p[i], bb2 = p[i | st];
                    p[i] = a + bb2;
                    p[i | st] = a - bb2;
                }
            }
        }
        __syncthreads();                 // all state reads complete; reuse SS
#pragma unroll
        for (int s = 0; s < 16; s++) SS[t * 17 + s] = p[s];
        float z[12];
#pragma unroll
        for (int w = 0; w < 12; w++) {
            float val = SS[t * 17 + sWtab[w]];
            z[w] = ((ptw >> w) & 1u) ? -val : val;
        }
#pragma unroll
        for (int w = 0; w < 12; w++) {
#pragma unroll
            for (int o = 16; o; o >>= 1)
                z[w] += __shfl_xor_sync(0xFFFFFFFFu, z[w], o);
        }
        if (lane == 0) {
#pragma unroll
            for (int w = 0; w < 12; w++) SS[4400 + warp * 12 + w] = z[w];
        }
        __syncthreads();
        if (t < 12) {
            float sum = 0.f;
#pragma unroll
            for (int wp = 0; wp < 8; wp++) sum += SS[4400 + wp * 12 + t];
            out[b * NQ + t] = sum;
        }
    }
#undef SRE
#undef SIM
}

// ---------------------------------------------------------------------------
extern "C" void kernel_launch(void* const* d_in, const int* in_sizes, int n_in,
                              void* d_out, int out_size) {
    const float* v = 0; const float* W = 0; const float* bc = 0; const float* wt = 0;
    for (int i = 0; i < n_in; i++) {
        if (in_sizes[i] == 4096 * 512)      v  = (const float*)d_in[i];
        else if (in_sizes[i] == 12 * 512)   W  = (const float*)d_in[i];
        else if (in_sizes[i] == 12)         bc = (const float*)d_in[i];
        else if (in_sizes[i] == 6 * 12 * 3) wt = (const float*)d_in[i];
    }
    float* out = (float*)d_out;

    setup_kernel<<<21, 512>>>(wt);

    void* pS = 0;
    cudaGetSymbolAddress(&pS, g_S);
    cudaMemcpyToSymbolAsync(cS, pS, sizeof(CParams), 0, cudaMemcpyDeviceToDevice, 0);

    qvl_kernel<<<4096, THREADS>>>(v, W, bc, out);
}

// round 16
// speedup vs baseline: 1.0545x; 1.0545x over previous
#include <cuda_runtime.h>

#define NQ 12
#define THREADS 256
#define PI_F 3.14159265358979323846f
typedef unsigned long long u64;

// Fused staging block (written by setup_kernel block 20), copied once into constant.
struct CParams {
    u64      G[165];     // RY coefficients, layers 1..5 (33 u64/layer)
    unsigned RM[72];     // CNOT masks: fwd layers 0..4, inverse layer 5
    float2   U0[48];     // layer-0 full Rot matrices (init fold)
};
__device__   CParams g_S;
__constant__ CParams cS;

__device__ ulonglong2 g_D2[5 * 2048];  // merged-diagonal, SoA-packed over (m, m+8):
                                       // entry (l,m,t) = {pk2(c_j0,c_j1), pk2(s_j0,s_j1)},
                                       // j0=(t<<4)|m, j1=j0|8; index (l<<11)|(m<<8)|t

__device__ __forceinline__ float2 cmul(float2 a, float2 b) {
    return make_float2(a.x * b.x - a.y * b.y, a.x * b.y + a.y * b.x);
}
__device__ __forceinline__ u64 pk2(float a, float b) {
    u64 r; asm("mov.b64 %0,{%1,%2};" : "=l"(r) : "f"(a), "f"(b)); return r;
}
__device__ __forceinline__ void unpk(u64 x, float& a, float& b) {
    asm("mov.b64 {%0,%1},%2;" : "=f"(a), "=f"(b) : "l"(x));
}
__device__ __forceinline__ u64 m2(u64 a, u64 b) {
    u64 d; asm("mul.rn.f32x2 %0,%1,%2;" : "=l"(d) : "l"(a), "l"(b)); return d;
}
__device__ __forceinline__ u64 fma2(u64 a, u64 b, u64 c) {
    u64 d; asm("fma.rn.f32x2 %0,%1,%2,%3;" : "=l"(d) : "l"(a), "l"(b), "l"(c)); return d;
}
__device__ __forceinline__ u64 swp(u64 x) {
    float lo, hi; unpk(x, lo, hi); return pk2(hi, lo);
}

// Forward CNOT-ring mask for layer l (0..4): image of basis bit bb under ring fold.
__device__ __forceinline__ unsigned ring_fwd_mask(int l, int bb) {
    unsigned i = 1u << bb;
    int r = (l % (NQ - 1)) + 1;
    for (int w = NQ - 1; w >= 0; --w)
        i ^= ((i >> w) & 1u) << ((w + r) % NQ);
    return i;
}

// ---------------------------------------------------------------------------
// Fused setup kernel.
//  blocks 0..19 (512 thr): diagonal table (10240 entries), ring masks inline.
//  block 20: staging struct g_S (layer-0 Rot fold, RY coeffs, CNOT masks).
// ---------------------------------------------------------------------------
__global__ void setup_kernel(const float* __restrict__ weights) {
    int tid = threadIdx.x;

    if (blockIdx.x == 20) {
        __shared__ float2 U[NQ][2][2];
        for (int w = tid; w < NQ; w += blockDim.x) {
            float phi = weights[w * 3 + 0];
            float th  = weights[w * 3 + 1];
            float om  = weights[w * 3 + 2];
            float s = sinf(0.5f * th), c = cosf(0.5f * th);
            float ap = 0.5f * (phi + om), am = 0.5f * (phi - om);
            float sap = sinf(ap), cap = cosf(ap);
            float sam = sinf(am), cam = cosf(am);
            U[w][0][0] = make_float2(cap * c, -sap * c);
            U[w][0][1] = make_float2(-cam * s, -sam * s);
            U[w][1][0] = make_float2(cam * s, -sam * s);
            U[w][1][1] = make_float2(cap * c, sap * c);
        }
        __syncthreads();
        for (int e = tid; e < NQ * 4; e += blockDim.x) {
            int w = e >> 2;
            g_S.U0[e] = U[w][(e >> 1) & 1][e & 1];
        }
        // RY coefficients for layers 1..5 (33 u64/layer, 11/config)
        if (tid < 15) {
            int l = tid / 3 + 1, c = tid % 3;
            int base = (l - 1) * 33 + c * 11;
            for (int bit = 0; bit < 4; bit++) {
                int q = c * 4 + bit;
                float th = weights[(l * NQ + q) * 3 + 1];
                float cc = cosf(0.5f * th), ss = sinf(0.5f * th);
                if (bit < 3) {
                    g_S.G[base + bit * 3 + 0] = pk2(cc, cc);
                    g_S.G[base + bit * 3 + 1] = pk2(ss, ss);
                    g_S.G[base + bit * 3 + 2] = pk2(-ss, -ss);
                } else {
                    g_S.G[base + 9]  = pk2(cc, cc);
                    g_S.G[base + 10] = pk2(-ss, ss);
                }
            }
        }
        // CNOT-ring masks: forward for layers 0..4, inverse for layer 5.
        for (int e = tid; e < 6 * NQ; e += blockDim.x) {
            int l = e / NQ, bb = e % NQ;
            unsigned i;
            if (l < 5) {
                i = ring_fwd_mask(l, bb);
            } else {
                i = 1u << bb;
                int r = (5 % (NQ - 1)) + 1;
                for (int w = 0; w < NQ; ++w)
                    i ^= ((i >> w) & 1u) << ((w + r) % NQ);
            }
            g_S.RM[e] = i;
        }
        return;
    }

    // Diagonal-table blocks. Entry math identical to R11:
    //   alpha(j) = sum_w (phi_{tl,w}/2)(2 b_w(j) - 1)
    //            + [tl>=2] sum_w (omega_{tl-1,w}/2)(2 b_w(R_{tl-1}(j)) - 1)
    int idx = blockIdx.x * 512 + tid;            // 0 .. 10239
    int l = idx >> 11;                           // 0..4 -> table layer l+1
    int rem = idx & 2047;
    int m = rem >> 8, t = rem & 255;
    float al[2];
#pragma unroll
    for (int h = 0; h < 2; h++) {
        unsigned j = ((unsigned)t << 4) | (unsigned)m | ((unsigned)h << 3);
        float a = 0.f;
        for (int w = 0; w < NQ; w++) {
            float phi = weights[((l + 1) * NQ + w) * 3 + 0];
            a += 0.5f * phi * (((j >> w) & 1u) ? 1.f : -1.f);
        }
        if (l >= 1) {
            unsigned rj = 0;
            for (int bb = 0; bb < NQ; bb++)
                if ((j >> bb) & 1u) rj ^= ring_fwd_mask(l, bb);
            for (int w = 0; w < NQ; w++) {
                float om = weights[(l * NQ + w) * 3 + 2];
                a += 0.5f * om * (((rj >> w) & 1u) ? 1.f : -1.f);
            }
        }
        al[h] = a;
    }
    ulonglong2 e;
    e.x = pk2(cosf(al[0]), cosf(al[1]));
    e.y = pk2(sinf(al[0]), sinf(al[1]));
    g_D2[((unsigned)l << 11) | ((unsigned)m << 8) | (unsigned)t] = e;
}

// ---------------------------------------------------------------------------
// RY gates on SoA packed registers (RE[m],IM[m] pack amp pair (m, m+8))
// ---------------------------------------------------------------------------
template <int Q>
__device__ __forceinline__ void bgate_ry(u64* RE, u64* IM, const u64* __restrict__ g) {
    u64 cc = g[0], ss = g[1], ns = g[2];
#pragma unroll
    for (int h = 0; h < 4; h++) {
        const int a = ((h >> Q) << (Q + 1)) | (h & ((1 << Q) - 1));
        const int bq = a + (1 << Q);
        u64 x0r = RE[a], x0i = IM[a], x1r = RE[bq], x1i = IM[bq];
        u64 y0r = m2(cc, x0r); y0r = fma2(ns, x1r, y0r);
        u64 y1r = m2(ss, x0r); y1r = fma2(cc, x1r, y1r);
        u64 y0i = m2(cc, x0i); y0i = fma2(ns, x1i, y0i);
        u64 y1i = m2(ss, x0i); y1i = fma2(cc, x1i, y1i);
        RE[a] = y0r; IM[a] = y0i; RE[bq] = y1r; IM[bq] = y1i;
    }
}

__device__ __forceinline__ void pgate_ry(u64* RE, u64* IM, const u64* __restrict__ g) {
    u64 P1 = g[0], P2 = g[1];     // (c,c), (-s,s)
#pragma unroll
    for (int m = 0; m < 8; m++) {
        u64 xr = RE[m], xi = IM[m];
        u64 yr = m2(P1, xr); yr = fma2(P2, swp(xr), yr);
        u64 yi = m2(P1, xi); yi = fma2(P2, swp(xi), yi);
        RE[m] = yr; IM[m] = yi;
    }
}

// ---------------------------------------------------------------------------
// Main kernel — R14 structure (#pragma unroll 1), plus a per-CTA SMEM table
// sTz[6][256]: pre-swizzled masked-read scatter bases for layers 1..5 and the
// raw expval sign mask (entry 5). Replaces the per-layer 8-term mask build
// (~110 ALU slots/thread) with one LDS.32 per layer.
// SMEM SoA, swizzle phi(j) = j ^ ((j>>4)&31).
// Config A: j=(t<<4)|m  Config B: j=(thi<<8)|(m<<4)|tlo  Config C: j=(m<<8)|t
// ---------------------------------------------------------------------------
__global__ void __launch_bounds__(THREADS, 4) qvl_kernel(
    const float* __restrict__ v, const float* __restrict__ W,
    const float* __restrict__ bc, float* __restrict__ out) {
    __shared__ float    SS[8192];      // [0..4095]=re, [4096..8191]=im
    __shared__ float2   sAH[40];
    __shared__ int      sWtab[12];
    __shared__ unsigned sTz[6 * 256];  // scatter-base tables
#define SRE(i) SS[(i)]
#define SIM(i) SS[4096 + (i)]

    int b = blockIdx.x, t = threadIdx.x;
    int lane = t & 31, warp = t >> 5;

    if (t < 12) {
        unsigned w = t;
        int s = (int)(((cS.RM[68] >> w) & 1u) | (((cS.RM[69] >> w) & 1u) << 1)
                    | (((cS.RM[70] >> w) & 1u) << 2) | (((cS.RM[71] >> w) & 1u) << 3));
        sWtab[t] = s;
    }

    // Build scatter-base tables (once per CTA): entry[l][tt] for l<5 is the
    // PRE-SWIZZLED base for the layer-(l+1) masked read; entry[5][tt] is the
    // raw expval sign mask (no swizzle).
#pragma unroll 1
    for (int e = t; e < 6 * 256; e += THREADS) {
        int lt = e >> 8, tt = e & 255;
        int off = (lt < 5) ? (lt * 12 + 4) : 60;
        unsigned mm = 0;
#pragma unroll
        for (int k = 0; k < 8; k++)
            mm ^= cS.RM[off + k] & (unsigned)(-(int)((tt >> k) & 1));
        if (lt < 5) mm ^= ((mm >> 4) & 31u);
        sTz[e] = mm;
    }

    // Angles: x_w = tanh(v[b]·W[w] + b[w]) * pi, fold layer-0 Rot
    const float* vrow = v + (size_t)b * 512;
    for (int w = warp; w < NQ; w += 8) {
        const float* Wr = W + w * 512;
        float acc = 0.f;
#pragma unroll
        for (int q = 0; q < 16; q++)
            acc = fmaf(vrow[lane + 32 * q], Wr[lane + 32 * q], acc);
#pragma unroll
        for (int o = 16; o; o >>= 1) acc += __shfl_xor_sync(0xFFFFFFFFu, acc, o);
        if (lane == 0) {
            float x = tanhf(acc + bc[w]) * PI_F;
            float ch = cosf(0.5f * x), sh = sinf(0.5f * x);
            float2 u00 = cS.U0[w * 4 + 0], u01 = cS.U0[w * 4 + 1];
            float2 u10 = cS.U0[w * 4 + 2], u11 = cS.U0[w * 4 + 3];
            sAH[2 * w + 0] = make_float2(u00.x * ch + u01.x * sh, u00.y * ch + u01.y * sh);
            sAH[2 * w + 1] = make_float2(u10.x * ch + u11.x * sh, u10.y * ch + u11.y * sh);
        }
    }
    __syncthreads();
    if (t < 16) {
        float2 h = sAH[16 + (t & 1)];
        h = cmul(h, sAH[18 + ((t >> 1) & 1)]);
        h = cmul(h, sAH[20 + ((t >> 2) & 1)]);
        h = cmul(h, sAH[22 + ((t >> 3) & 1)]);
        sAH[24 + t] = h;
    }
    __syncthreads();

    unsigned xC = (unsigned)t ^ (((unsigned)t >> 4) & 15u);
    unsigned xA = ((unsigned)t << 4) ^ ((unsigned)t & 31u);
    unsigned xB = ((((unsigned)t >> 4) << 8) | ((unsigned)t & 15u)) ^ ((((unsigned)t >> 4) & 1u) << 4);

    // Product-state init -> config C positions
    {
        float2 tp = sAH[t & 1];
#pragma unroll
        for (int w = 1; w < 8; w++)
            tp = cmul(tp, sAH[2 * w + ((t >> w) & 1)]);
#pragma unroll
        for (int m = 0; m < 16; m++) {
            float2 a = cmul(tp, sAH[24 + m]);
            unsigned ad = ((unsigned)m << 8) ^ xC ^ (((unsigned)m & 1u) << 4);
            SRE(ad) = a.x; SIM(ad) = a.y;
        }
    }
    __syncthreads();

    u64 RE[8], IM[8];

#pragma unroll 1
    for (int l = 1; l <= 5; l++) {
        const u64* gl = cS.G + (l - 1) * 33;
        const unsigned* rm = cS.RM + (l - 1) * 12;

        // ---- prefetch SoA-packed diagonal entries (coalesced LDG.128) ----
        const ulonglong2* Dl = g_D2 + ((l - 1) << 11) + t;
        ulonglong2 dd[8];
#pragma unroll
        for (int m = 0; m < 8; m++)
            dd[m] = Dl[m << 8];

        // ---- masked read into config A (CNOT ring of layer l-1 folded) ----
        unsigned sbz = sTz[(l - 1) * 256 + t];   // pre-swizzled base
        unsigned r0 = rm[0], r1 = rm[1], r2 = rm[2], r3 = rm[3];
        unsigned z0 = r0 ^ ((r0 >> 4) & 31u);
        unsigned z1 = r1 ^ ((r1 >> 4) & 31u);
        unsigned z2 = r2 ^ ((r2 >> 4) & 31u);
        unsigned z3 = r3 ^ ((r3 >> 4) & 31u);
#pragma unroll
        for (int m = 0; m < 8; m++) {
            unsigned a0 = sbz;
            if (m & 1) a0 ^= z0;
            if (m & 2) a0 ^= z1;
            if (m & 4) a0 ^= z2;
            unsigned a1 = a0 ^ z3;
            RE[m] = pk2(SRE(a0), SRE(a1));
            IM[m] = pk2(SIM(a0), SIM(a1));
        }

        // ---- merged diagonal (pushed-through RZ walls), dest amp j=(t<<4)|m ----
#pragma unroll
        for (int m = 0; m < 8; m++) {
            u64 c2 = dd[m].x;
            u64 s2 = dd[m].y;
            u64 ns2 = s2 ^ 0x8000000080000000ULL;
            u64 nr = m2(c2, RE[m]); nr = fma2(ns2, IM[m], nr);
            u64 ni = m2(c2, IM[m]); ni = fma2(s2, RE[m], ni);
            RE[m] = nr; IM[m] = ni;
        }

        bgate_ry<0>(RE, IM, gl + 0);   // q0
        bgate_ry<1>(RE, IM, gl + 3);   // q1
        bgate_ry<2>(RE, IM, gl + 6);   // q2
        pgate_ry(RE, IM, gl + 9);      // q3 (pack bit)
        __syncthreads();               // all masked reads done before write A
#pragma unroll
        for (int m = 0; m < 8; m++) {  // write A
            unsigned a0 = xA ^ (unsigned)m, a1 = a0 ^ 8u;
            float lo, hi;
            unpk(RE[m], lo, hi); SRE(a0) = lo; SRE(a1) = hi;
            unpk(IM[m], lo, hi); SIM(a0) = lo; SIM(a1) = hi;
        }
        __syncwarp();                  // A<->B exchange within 16-thread groups
#pragma unroll
        for (int m = 0; m < 8; m++) {  // read B
            unsigned a0 = xB ^ (unsigned)(m * 17), a1 = a0 ^ 136u;
            RE[m] = pk2(SRE(a0), SRE(a1));
            IM[m] = pk2(SIM(a0), SIM(a1));
        }
        bgate_ry<0>(RE, IM, gl + 11);  // q4
        bgate_ry<1>(RE, IM, gl + 14);  // q5
        bgate_ry<2>(RE, IM, gl + 17);  // q6
        pgate_ry(RE, IM, gl + 20);     // q7 (pack bit)
#pragma unroll
        for (int m = 0; m < 8; m++) {  // write B (same per-thread set)
            unsigned a0 = xB ^ (unsigned)(m * 17), a1 = a0 ^ 136u;
            float lo, hi;
            unpk(RE[m], lo, hi); SRE(a0) = lo; SRE(a1) = hi;
            unpk(IM[m], lo, hi); SIM(a0) = lo; SIM(a1) = hi;
        }
        __syncthreads();               // B->C crosses the whole CTA
#pragma unroll
        for (int m = 0; m < 8; m++) {  // read C
            unsigned a0 = xC ^ ((unsigned)m << 8) ^ (((unsigned)m & 1u) << 4);
            unsigned a1 = a0 ^ 2048u;
            RE[m] = pk2(SRE(a0), SRE(a1));
            IM[m] = pk2(SIM(a0), SIM(a1));
        }
        bgate_ry<0>(RE, IM, gl + 22);  // q8
        bgate_ry<1>(RE, IM, gl + 25);  // q9
        bgate_ry<2>(RE, IM, gl + 28);  // q10
        pgate_ry(RE, IM, gl + 31);     // q11 (pack bit)
        if (l < 5) {
#pragma unroll
            for (int m = 0; m < 8; m++) {  // write C (same per-thread set)
                unsigned a0 = xC ^ ((unsigned)m << 8) ^ (((unsigned)m & 1u) << 4);
                unsigned a1 = a0 ^ 2048u;
                float lo, hi;
                unpk(RE[m], lo, hi); SRE(a0) = lo; SRE(a1) = hi;
                unpk(IM[m], lo, hi); SIM(a0) = lo; SIM(a1) = hi;
            }
            __syncthreads();
        }
    }

    // ---- Expvals via 4-level Walsh transform over the m-bits ----
    // (Final RZ wall is a pure phase: cancels in |amp|^2. Ring_5 via inverse masks.)
    {
        unsigned ptw = sTz[5 * 256 + t];

        float p[16];
#pragma unroll
        for (int m = 0; m < 8; m++) {
            u64 P = m2(RE[m], RE[m]);
            P = fma2(IM[m], IM[m], P);
            unpk(P, p[m], p[m + 8]);
        }
#pragma unroll
        for (int st = 1; st < 16; st <<= 1) {
#pragma unroll
            for (int i = 0; i < 16; i++) {
                if (!(i & st)) {
                    float a = p[i], bb2 = p[i | st];
                    p[i] = a + bb2;
                    p[i | st] = a - bb2;
                }
            }
        }
        __syncthreads();                 // all state reads complete; reuse SS
#pragma unroll
        for (int s = 0; s < 16; s++) SS[t * 17 + s] = p[s];
        float z[12];
#pragma unroll
        for (int w = 0; w < 12; w++) {
            float val = SS[t * 17 + sWtab[w]];
            z[w] = ((ptw >> w) & 1u) ? -val : val;
        }
#pragma unroll
        for (int w = 0; w < 12; w++) {
#pragma unroll
            for (int o = 16; o; o >>= 1)
                z[w] += __shfl_xor_sync(0xFFFFFFFFu, z[w], o);
        }
        if (lane == 0) {
#pragma unroll
            for (int w = 0; w < 12; w++) SS[4400 + warp * 12 + w] = z[w];
        }
        __syncthreads();
        if (t < 12) {
            float sum = 0.f;
#pragma unroll
            for (int wp = 0; wp < 8; wp++) sum += SS[4400 + wp * 12 + t];
            out[b * NQ + t] = sum;
        }
    }
#undef SRE
#undef SIM
}

// ---------------------------------------------------------------------------
extern "C" void kernel_launch(void* const* d_in, const int* in_sizes, int n_in,
                              void* d_out, int out_size) {
    const float* v = 0; const float* W = 0; const float* bc = 0; const float* wt = 0;
    for (int i = 0; i < n_in; i++) {
        if (in_sizes[i] == 4096 * 512)      v  = (const float*)d_in[i];
        else if (in_sizes[i] == 12 * 512)   W  = (const float*)d_in[i];
        else if (in_sizes[i] == 12)         bc = (const float*)d_in[i];
        else if (in_sizes[i] == 6 * 12 * 3) wt = (const float*)d_in[i];
    }
    float* out = (float*)d_out;

    setup_kernel<<<21, 512>>>(wt);

    void* pS = 0;
    cudaGetSymbolAddress(&pS, g_S);
    cudaMemcpyToSymbolAsync(cS, pS, sizeof(CParams), 0, cudaMemcpyDeviceToDevice, 0);

    qvl_kernel<<<4096, THREADS>>>(v, W, bc, out);
}

// round 17
// speedup vs baseline: 1.0898x; 1.0334x over previous
#include <cuda_runtime.h>

#define NQ 12
#define THREADS 256
#define PI_F 3.14159265358979323846f
typedef unsigned long long u64;

// Fused staging block (written by setup_kernel block 20), copied once into constant.
struct CParams {
    u64      G[165];     // RY coefficients, layers 1..5 (33 u64/layer)
    unsigned RM[72];     // CNOT masks: fwd layers 0..4, inverse layer 5
    float2   U0[48];     // layer-0 full Rot matrices (init fold)
};
__device__   CParams g_S;
__constant__ CParams cS;

__device__ ulonglong2 g_D2[5 * 2048];  // merged-diagonal, SoA-packed over (m, m+8):
                                       // entry (l,m,t) = {pk2(c_j0,c_j1), pk2(s_j0,s_j1)},
                                       // j0=(t<<4)|m, j1=j0|8; index (l<<11)|(m<<8)|t

__device__ __forceinline__ float2 cmul(float2 a, float2 b) {
    return make_float2(a.x * b.x - a.y * b.y, a.x * b.y + a.y * b.x);
}
__device__ __forceinline__ u64 pk2(float a, float b) {
    u64 r; asm("mov.b64 %0,{%1,%2};" : "=l"(r) : "f"(a), "f"(b)); return r;
}
__device__ __forceinline__ void unpk(u64 x, float& a, float& b) {
    asm("mov.b64 {%0,%1},%2;" : "=f"(a), "=f"(b) : "l"(x));
}
__device__ __forceinline__ u64 m2(u64 a, u64 b) {
    u64 d; asm("mul.rn.f32x2 %0,%1,%2;" : "=l"(d) : "l"(a), "l"(b)); return d;
}
__device__ __forceinline__ u64 fma2(u64 a, u64 b, u64 c) {
    u64 d; asm("fma.rn.f32x2 %0,%1,%2,%3;" : "=l"(d) : "l"(a), "l"(b), "l"(c)); return d;
}
__device__ __forceinline__ u64 swp(u64 x) {
    float lo, hi; unpk(x, lo, hi); return pk2(hi, lo);
}

// Forward CNOT-ring mask for layer l (0..4): image of basis bit bb under ring fold.
__device__ __forceinline__ unsigned ring_fwd_mask(int l, int bb) {
    unsigned i = 1u << bb;
    int r = (l % (NQ - 1)) + 1;
    for (int w = NQ - 1; w >= 0; --w)
        i ^= ((i >> w) & 1u) << ((w + r) % NQ);
    return i;
}

// ---------------------------------------------------------------------------
// Fused setup kernel.
//  blocks 0..19 (512 thr): diagonal table (10240 entries), ring masks inline.
//  block 20: staging struct g_S (layer-0 Rot fold, RY coeffs, CNOT masks).
// ---------------------------------------------------------------------------
__global__ void setup_kernel(const float* __restrict__ weights) {
    int tid = threadIdx.x;

    if (blockIdx.x == 20) {
        __shared__ float2 U[NQ][2][2];
        for (int w = tid; w < NQ; w += blockDim.x) {
            float phi = weights[w * 3 + 0];
            float th  = weights[w * 3 + 1];
            float om  = weights[w * 3 + 2];
            float s = sinf(0.5f * th), c = cosf(0.5f * th);
            float ap = 0.5f * (phi + om), am = 0.5f * (phi - om);
            float sap = sinf(ap), cap = cosf(ap);
            float sam = sinf(am), cam = cosf(am);
            U[w][0][0] = make_float2(cap * c, -sap * c);
            U[w][0][1] = make_float2(-cam * s, -sam * s);
            U[w][1][0] = make_float2(cam * s, -sam * s);
            U[w][1][1] = make_float2(cap * c, sap * c);
        }
        __syncthreads();
        for (int e = tid; e < NQ * 4; e += blockDim.x) {
            int w = e >> 2;
            g_S.U0[e] = U[w][(e >> 1) & 1][e & 1];
        }
        // RY coefficients for layers 1..5 (33 u64/layer, 11/config)
        if (tid < 15) {
            int l = tid / 3 + 1, c = tid % 3;
            int base = (l - 1) * 33 + c * 11;
            for (int bit = 0; bit < 4; bit++) {
                int q = c * 4 + bit;
                float th = weights[(l * NQ + q) * 3 + 1];
                float cc = cosf(0.5f * th), ss = sinf(0.5f * th);
                if (bit < 3) {
                    g_S.G[base + bit * 3 + 0] = pk2(cc, cc);
                    g_S.G[base + bit * 3 + 1] = pk2(ss, ss);
                    g_S.G[base + bit * 3 + 2] = pk2(-ss, -ss);
                } else {
                    g_S.G[base + 9]  = pk2(cc, cc);
                    g_S.G[base + 10] = pk2(-ss, ss);
                }
            }
        }
        // CNOT-ring masks: forward for layers 0..4, inverse for layer 5.
        for (int e = tid; e < 6 * NQ; e += blockDim.x) {
            int l = e / NQ, bb = e % NQ;
            unsigned i;
            if (l < 5) {
                i = ring_fwd_mask(l, bb);
            } else {
                i = 1u << bb;
                int r = (5 % (NQ - 1)) + 1;
                for (int w = 0; w < NQ; ++w)
                    i ^= ((i >> w) & 1u) << ((w + r) % NQ);
            }
            g_S.RM[e] = i;
        }
        return;
    }

    // Diagonal-table blocks. Entry math identical to R11:
    //   alpha(j) = sum_w (phi_{tl,w}/2)(2 b_w(j) - 1)
    //            + [tl>=2] sum_w (omega_{tl-1,w}/2)(2 b_w(R_{tl-1}(j)) - 1)
    int idx = blockIdx.x * 512 + tid;            // 0 .. 10239
    int l = idx >> 11;                           // 0..4 -> table layer l+1
    int rem = idx & 2047;
    int m = rem >> 8, t = rem & 255;
    float al[2];
#pragma unroll
    for (int h = 0; h < 2; h++) {
        unsigned j = ((unsigned)t << 4) | (unsigned)m | ((unsigned)h << 3);
        float a = 0.f;
        for (int w = 0; w < NQ; w++) {
            float phi = weights[((l + 1) * NQ + w) * 3 + 0];
            a += 0.5f * phi * (((j >> w) & 1u) ? 1.f : -1.f);
        }
        if (l >= 1) {
            unsigned rj = 0;
            for (int bb = 0; bb < NQ; bb++)
                if ((j >> bb) & 1u) rj ^= ring_fwd_mask(l, bb);
            for (int w = 0; w < NQ; w++) {
                float om = weights[(l * NQ + w) * 3 + 2];
                a += 0.5f * om * (((rj >> w) & 1u) ? 1.f : -1.f);
            }
        }
        al[h] = a;
    }
    ulonglong2 e;
    e.x = pk2(cosf(al[0]), cosf(al[1]));
    e.y = pk2(sinf(al[0]), sinf(al[1]));
    g_D2[((unsigned)l << 11) | ((unsigned)m << 8) | (unsigned)t] = e;
}

// ---------------------------------------------------------------------------
// RY gates on SoA packed registers (RE[m],IM[m] pack amp pair (m, m+8))
// ---------------------------------------------------------------------------
template <int Q>
__device__ __forceinline__ void bgate_ry(u64* RE, u64* IM, const u64* __restrict__ g) {
    u64 cc = g[0], ss = g[1], ns = g[2];
#pragma unroll
    for (int h = 0; h < 4; h++) {
        const int a = ((h >> Q) << (Q + 1)) | (h & ((1 << Q) - 1));
        const int bq = a + (1 << Q);
        u64 x0r = RE[a], x0i = IM[a], x1r = RE[bq], x1i = IM[bq];
        u64 y0r = m2(cc, x0r); y0r = fma2(ns, x1r, y0r);
        u64 y1r = m2(ss, x0r); y1r = fma2(cc, x1r, y1r);
        u64 y0i = m2(cc, x0i); y0i = fma2(ns, x1i, y0i);
        u64 y1i = m2(ss, x0i); y1i = fma2(cc, x1i, y1i);
        RE[a] = y0r; IM[a] = y0i; RE[bq] = y1r; IM[bq] = y1i;
    }
}

__device__ __forceinline__ void pgate_ry(u64* RE, u64* IM, const u64* __restrict__ g) {
    u64 P1 = g[0], P2 = g[1];     // (c,c), (-s,s)
#pragma unroll
    for (int m = 0; m < 8; m++) {
        u64 xr = RE[m], xi = IM[m];
        u64 yr = m2(P1, xr); yr = fma2(P2, swp(xr), yr);
        u64 yi = m2(P1, xi); yi = fma2(P2, swp(xi), yi);
        RE[m] = yr; IM[m] = yi;
    }
}

// ---------------------------------------------------------------------------
// Main kernel — the converged R14 configuration (best measured: 227.4 us).
// SMEM SoA, swizzle phi(j) = j ^ ((j>>4)&31).
// Config A: j=(t<<4)|m  Config B: j=(thi<<8)|(m<<4)|tlo  Config C: j=(m<<8)|t
// ---------------------------------------------------------------------------
__global__ void __launch_bounds__(THREADS, 4) qvl_kernel(
    const float* __restrict__ v, const float* __restrict__ W,
    const float* __restrict__ bc, float* __restrict__ out) {
    __shared__ float  SS[8192];        // [0..4095]=re, [4096..8191]=im
    __shared__ float2 sAH[40];
    __shared__ int    sWtab[12];
#define SRE(i) SS[(i)]
#define SIM(i) SS[4096 + (i)]

    int b = blockIdx.x, t = threadIdx.x;
    int lane = t & 31, warp = t >> 5;

    if (t < 12) {
        unsigned w = t;
        int s = (int)(((cS.RM[68] >> w) & 1u) | (((cS.RM[69] >> w) & 1u) << 1)
                    | (((cS.RM[70] >> w) & 1u) << 2) | (((cS.RM[71] >> w) & 1u) << 3));
        sWtab[t] = s;
    }

    // Angles: x_w = tanh(v[b]·W[w] + b[w]) * pi, fold layer-0 Rot
    const float* vrow = v + (size_t)b * 512;
    for (int w = warp; w < NQ; w += 8) {
        const float* Wr = W + w * 512;
        float acc = 0.f;
#pragma unroll
        for (int q = 0; q < 16; q++)
            acc = fmaf(vrow[lane + 32 * q], Wr[lane + 32 * q], acc);
#pragma unroll
        for (int o = 16; o; o >>= 1) acc += __shfl_xor_sync(0xFFFFFFFFu, acc, o);
        if (lane == 0) {
            float x = tanhf(acc + bc[w]) * PI_F;
            float ch = cosf(0.5f * x), sh = sinf(0.5f * x);
            float2 u00 = cS.U0[w * 4 + 0], u01 = cS.U0[w * 4 + 1];
            float2 u10 = cS.U0[w * 4 + 2], u11 = cS.U0[w * 4 + 3];
            sAH[2 * w + 0] = make_float2(u00.x * ch + u01.x * sh, u00.y * ch + u01.y * sh);
            sAH[2 * w + 1] = make_float2(u10.x * ch + u11.x * sh, u10.y * ch + u11.y * sh);
        }
    }
    __syncthreads();
    if (t < 16) {
        float2 h = sAH[16 + (t & 1)];
        h = cmul(h, sAH[18 + ((t >> 1) & 1)]);
        h = cmul(h, sAH[20 + ((t >> 2) & 1)]);
        h = cmul(h, sAH[22 + ((t >> 3) & 1)]);
        sAH[24 + t] = h;
    }
    __syncthreads();

    unsigned xC = (unsigned)t ^ (((unsigned)t >> 4) & 15u);
    unsigned xA = ((unsigned)t << 4) ^ ((unsigned)t & 31u);
    unsigned xB = ((((unsigned)t >> 4) << 8) | ((unsigned)t & 15u)) ^ ((((unsigned)t >> 4) & 1u) << 4);

    // Product-state init -> config C positions
    {
        float2 tp = sAH[t & 1];
#pragma unroll
        for (int w = 1; w < 8; w++)
            tp = cmul(tp, sAH[2 * w + ((t >> w) & 1)]);
#pragma unroll
        for (int m = 0; m < 16; m++) {
            float2 a = cmul(tp, sAH[24 + m]);
            unsigned ad = ((unsigned)m << 8) ^ xC ^ (((unsigned)m & 1u) << 4);
            SRE(ad) = a.x; SIM(ad) = a.y;
        }
    }
    __syncthreads();

    u64 RE[8], IM[8];

#pragma unroll 1
    for (int l = 1; l <= 5; l++) {
        const u64* gl = cS.G + (l - 1) * 33;
        const unsigned* rm = cS.RM + (l - 1) * 12;

        // ---- prefetch SoA-packed diagonal entries (coalesced LDG.128) ----
        const ulonglong2* Dl = g_D2 + ((l - 1) << 11) + t;
        ulonglong2 dd[8];
#pragma unroll
        for (int m = 0; m < 8; m++)
            dd[m] = Dl[m << 8];

        // ---- masked read into config A (CNOT ring of layer l-1 folded) ----
        unsigned sb = 0;
#pragma unroll
        for (int k = 0; k < 8; k++)
            sb ^= rm[4 + k] & (unsigned)(-(int)((t >> k) & 1));
        unsigned sbz = sb ^ ((sb >> 4) & 31u);
        unsigned r0 = rm[0], r1 = rm[1], r2 = rm[2], r3 = rm[3];
        unsigned z0 = r0 ^ ((r0 >> 4) & 31u);
        unsigned z1 = r1 ^ ((r1 >> 4) & 31u);
        unsigned z2 = r2 ^ ((r2 >> 4) & 31u);
        unsigned z3 = r3 ^ ((r3 >> 4) & 31u);
#pragma unroll
        for (int m = 0; m < 8; m++) {
            unsigned a0 = sbz;
            if (m & 1) a0 ^= z0;
            if (m & 2) a0 ^= z1;
            if (m & 4) a0 ^= z2;
            unsigned a1 = a0 ^ z3;
            RE[m] = pk2(SRE(a0), SRE(a1));
            IM[m] = pk2(SIM(a0), SIM(a1));
        }

        // ---- merged diagonal (pushed-through RZ walls), dest amp j=(t<<4)|m ----
#pragma unroll
        for (int m = 0; m < 8; m++) {
            u64 c2 = dd[m].x;
            u64 s2 = dd[m].y;
            u64 ns2 = s2 ^ 0x8000000080000000ULL;
            u64 nr = m2(c2, RE[m]); nr = fma2(ns2, IM[m], nr);
            u64 ni = m2(c2, IM[m]); ni = fma2(s2, RE[m], ni);
            RE[m] = nr; IM[m] = ni;
        }

        bgate_ry<0>(RE, IM, gl + 0);   // q0
        bgate_ry<1>(RE, IM, gl + 3);   // q1
        bgate_ry<2>(RE, IM, gl + 6);   // q2
        pgate_ry(RE, IM, gl + 9);      // q3 (pack bit)
        __syncthreads();               // all masked reads done before write A
#pragma unroll
        for (int m = 0; m < 8; m++) {  // write A
            unsigned a0 = xA ^ (unsigned)m, a1 = a0 ^ 8u;
            float lo, hi;
            unpk(RE[m], lo, hi); SRE(a0) = lo; SRE(a1) = hi;
            unpk(IM[m], lo, hi); SIM(a0) = lo; SIM(a1) = hi;
        }
        __syncwarp();                  // A<->B exchange within 16-thread groups
#pragma unroll
        for (int m = 0; m < 8; m++) {  // read B
            unsigned a0 = xB ^ (unsigned)(m * 17), a1 = a0 ^ 136u;
            RE[m] = pk2(SRE(a0), SRE(a1));
            IM[m] = pk2(SIM(a0), SIM(a1));
        }
        bgate_ry<0>(RE, IM, gl + 11);  // q4
        bgate_ry<1>(RE, IM, gl + 14);  // q5
        bgate_ry<2>(RE, IM, gl + 17);  // q6
        pgate_ry(RE, IM, gl + 20);     // q7 (pack bit)
#pragma unroll
        for (int m = 0; m < 8; m++) {  // write B (same per-thread set)
            unsigned a0 = xB ^ (unsigned)(m * 17), a1 = a0 ^ 136u;
            float lo, hi;
            unpk(RE[m], lo, hi); SRE(a0) = lo; SRE(a1) = hi;
            unpk(IM[m], lo, hi); SIM(a0) = lo; SIM(a1) = hi;
        }
        __syncthreads();               // B->C crosses the whole CTA
#pragma unroll
        for (int m = 0; m < 8; m++) {  // read C
            unsigned a0 = xC ^ ((unsigned)m << 8) ^ (((unsigned)m & 1u) << 4);
            unsigned a1 = a0 ^ 2048u;
            RE[m] = pk2(SRE(a0), SRE(a1));
            IM[m] = pk2(SIM(a0), SIM(a1));
        }
        bgate_ry<0>(RE, IM, gl + 22);  // q8
        bgate_ry<1>(RE, IM, gl + 25);  // q9
        bgate_ry<2>(RE, IM, gl + 28);  // q10
        pgate_ry(RE, IM, gl + 31);     // q11 (pack bit)
        if (l < 5) {
#pragma unroll
            for (int m = 0; m < 8; m++) {  // write C (same per-thread set)
                unsigned a0 = xC ^ ((unsigned)m << 8) ^ (((unsigned)m & 1u) << 4);
                unsigned a1 = a0 ^ 2048u;
                float lo, hi;
                unpk(RE[m], lo, hi); SRE(a0) = lo; SRE(a1) = hi;
                unpk(IM[m], lo, hi); SIM(a0) = lo; SIM(a1) = hi;
            }
            __syncthreads();
        }
    }

    // ---- Expvals via 4-level Walsh transform over the m-bits ----
    // (Final RZ wall is a pure phase: cancels in |amp|^2. Ring_5 via inverse masks.)
    {
        unsigned ptw = 0;
#pragma unroll
        for (int k = 0; k < 8; k++)
            ptw ^= cS.RM[60 + k] & (unsigned)(-(int)((t >> k) & 1));

        float p[16];
#pragma unroll
        for (int m = 0; m < 8; m++) {
            u64 P = m2(RE[m], RE[m]);
            P = fma2(IM[m], IM[m], P);
            unpk(P, p[m], p[m + 8]);
        }
#pragma unroll
        for (int st = 1; st < 16; st <<= 1) {
#pragma unroll
            for (int i = 0; i < 16; i++) {
                if (!(i & st)) {
                    float a = p[i], bb2 = p[i | st];
                    p[i] = a + bb2;
                    p[i | st] = a - bb2;
                }
            }
        }
        __syncthreads();                 // all state reads complete; reuse SS
#pragma unroll
        for (int s = 0; s < 16; s++) SS[t * 17 + s] = p[s];
        float z[12];
#pragma unroll
        for (int w = 0; w < 12; w++) {
            float val = SS[t * 17 + sWtab[w]];
            z[w] = ((ptw >> w) & 1u) ? -val : val;
        }
#pragma unroll
        for (int w = 0; w < 12; w++) {
#pragma unroll
            for (int o = 16; o; o >>= 1)
                z[w] += __shfl_xor_sync(0xFFFFFFFFu, z[w], o);
        }
        if (lane == 0) {
#pragma unroll
            for (int w = 0; w < 12; w++) SS[4400 + warp * 12 + w] = z[w];
        }
        __syncthreads();
        if (t < 12) {
            float sum = 0.f;
#pragma unroll
            for (int wp = 0; wp < 8; wp++) sum += SS[4400 + wp * 12 + t];
            out[b * NQ + t] = sum;
        }
    }
#undef SRE
#undef SIM
}

// ---------------------------------------------------------------------------
extern "C" void kernel_launch(void* const* d_in, const int* in_sizes, int n_in,
                              void* d_out, int out_size) {
    const float* v = 0; const float* W = 0; const float* bc = 0; const float* wt = 0;
    for (int i = 0; i < n_in; i++) {
        if (in_sizes[i] == 4096 * 512)      v  = (const float*)d_in[i];
        else if (in_sizes[i] == 12 * 512)   W  = (const float*)d_in[i];
        else if (in_sizes[i] == 12)         bc = (const float*)d_in[i];
        else if (in_sizes[i] == 6 * 12 * 3) wt = (const float*)d_in[i];
    }
    float* out = (float*)d_out;

    setup_kernel<<<21, 512>>>(wt);

    void* pS = 0;
    cudaGetSymbolAddress(&pS, g_S);
    cudaMemcpyToSymbolAsync(cS, pS, sizeof(CParams), 0, cudaMemcpyDeviceToDevice, 0);

    qvl_kernel<<<4096, THREADS>>>(v, W, bc, out);
}